// round 7
// baseline (speedup 1.0000x reference)
#include <cuda_runtime.h>
#include <cuda_bf16.h>

// LIF recurrent scan, v5: speculative chunks + deep register prefetch,
// 1024 threads (VPT=1) for 4x latency hiding.
//
// 1 CTA per batch row; membrane state (1 float/thread) in registers for all T
// steps; recurrent GEMM is a sparse rank-k update from a shared spike list
// (~6.5e-6 dense). Chunks of 10 steps run speculatively with no barriers and
// no act computation; any mid-chunk spike (state >= 1.0) sets a flag and the
// chunk is replayed exactly with per-step barriers (rare). Each chunk batches
// the next chunk's 10 x-loads (MLP=10) into a register ring.
//
// v5 change (from ncu evidence): v4 was latency-bound at occ=12.5% (2 warps
// per scheduler). 1024 threads -> 32 warps/SM -> every exposed latency (LDS,
// pred guards, STG cost, FFMA chains, barrier spread) is now hideable.

#define N_NEU   1024
#define THREADS 1024
#define CHUNK   10           // steps per chunk; T=1000 = 50 * (2*CHUNK)

__device__ __forceinline__ void do_chunk(
    int tc, int T,
    float (&xcur)[CHUNK], float (&xnxt)[CHUNK],
    float& state, float brec, float db,
    const float* __restrict__ W,
    const float* __restrict__ xb,
    float* __restrict__ op,
    int tid,
    int (&s_idx)[2][N_NEU], float (&s_val)[2][N_NEU],
    int (&s_cnt)[2], int& s_flag,
    int& pb, int& qb)
{
    const float ALPHA = 0.9f;
    const float OMA   = 1.0f - 0.9f;

    // ---- prefetch next chunk: CHUNK independent LDG.32s (MLP=CHUNK) ----
#pragma unroll
    for (int s = 0; s < CHUNK; s++) {
        const int tp = min(tc + CHUNK + s, T - 1);   // clamped; tail garbage unused
        xnxt[s] = xb[(size_t)tp * N_NEU];
    }

    const int c_prev = s_cnt[pb];
    const float snap = state;

    // ---------- fast speculative pass: no loads, no barriers, no act ----------
#pragma unroll
    for (int s = 0; s < CHUNK - 1; s++) {
        float rec0 = 0.0f;                 // extra rec beyond bias (step 0 only)
        if (s == 0) {                      // compile-time branch
            for (int k = 0; k < c_prev; k++) {
                const int   j = s_idx[pb][k];
                const float v = s_val[pb][k];
                rec0 = fmaf(v, W[(size_t)tid * N_NEU + j], rec0);
            }
        }

        // spike detector only: state >= 1.0 forces replay of this chunk
        if (state >= 1.0f) s_flag = 1;     // single predicated STS (rare)

        // speculative output: zero (replay overwrites on mis-speculation)
        op[(size_t)(tc + s) * N_NEU] = 0.0f;

        // membrane update with act = 0:
        //   state = state*0.9 + 0.1*(x + brec + rec0)
        // computed exactly as the reference ordering: tot = x + rec
        const float tot = xcur[s] + (brec + rec0);   // rec = bias (+rank-k at s==0)
        state = state * ALPHA + OMA * tot;
    }

    // ---------- last step of chunk: full exact path (spikes feed next) ----------
    {
        const float sv  = state;
        const float act = (sv > 0.0f) ? floorf(sv) : 0.0f;
        if (act != 0.0f) {                            // rare push
            const int p = atomicAdd(&s_cnt[qb], 1);
            s_idx[qb][p] = tid;
            s_val[qb][p] = act;
        }

        op[(size_t)(tc + CHUNK - 1) * N_NEU] = act;

        const float tot = xcur[CHUNK - 1] + brec;     // rec = bias for s > 0
        const float st  = state - act;
        state = st * ALPHA + OMA * tot;
    }

    __syncthreads();                    // B1: flag & pushes visible
    const int f = s_flag;
    if (tid == 0 && !f) s_cnt[pb] = 0;  // retire prev list (commit only)
    __syncthreads();                    // B2: flag consumed by all

    if (f) {
        // ---------- rollback: exact replay with per-step barriers ----------
        state = snap;
        if (tid == 0) { s_cnt[qb] = 0; s_flag = 0; }
        __syncthreads();

        int rb = pb, wb = qb;
#pragma unroll 1
        for (int s = 0; s < CHUNK; s++) {
            const int t = tc + s;
            const int c = s_cnt[rb];
            const float xv = xb[(size_t)t * N_NEU];   // same value as xcur[s]

            float rec = brec;
            for (int k = 0; k < c; k++) {
                const int   j = s_idx[rb][k];
                const float v = s_val[rb][k];
                rec = fmaf(v, W[(size_t)tid * N_NEU + j], rec);
            }

            const float sv  = state;
            const float act = (sv > 0.0f) ? floorf(sv) : 0.0f;
            if (act != 0.0f) {
                const int p = atomicAdd(&s_cnt[wb], 1);
                s_idx[wb][p] = tid;
                s_val[wb][p] = act;
            }

            op[(size_t)t * N_NEU] = act;

            const float tot = xv + rec;
            const float st  = state - act;
            state = st * ALPHA + OMA * tot;

            __syncthreads();
            if (tid == 0) s_cnt[rb] = 0;
            __syncthreads();
            const int tmp = rb; rb = wb; wb = tmp;
        }
        pb = rb; qb = wb;   // last step's spikes live in rb; wb count is 0
    } else {
        const int tmp = pb; pb = qb; qb = tmp;
    }
}

__global__ __launch_bounds__(THREADS, 1)
void lif_recurrent_kernel(const float* __restrict__ x,     // [B, T, N]
                          const float* __restrict__ W,     // [N, N] (out, in)
                          const float* __restrict__ bias,  // [N]
                          float* __restrict__ out,         // [B, T, N]
                          int T)
{
    const int b   = blockIdx.x;
    const int tid = threadIdx.x;

    __shared__ int   s_idx[2][N_NEU];
    __shared__ float s_val[2][N_NEU];
    __shared__ int   s_cnt[2];
    __shared__ int   s_flag;
    if (tid < 2) s_cnt[tid] = 0;
    if (tid == 0) s_flag = 0;
    __syncthreads();

    float state = 0.0f;
    const float brec = bias[tid];
    const float db   = 0.1f * brec;   // (kept for interface; not load-bearing)

    const float* xb = x   + (size_t)b * T * N_NEU + tid;
    float*       op = out + (size_t)b * T * N_NEU + tid;

    // preload chunk 0 into buffer A
    float xA[CHUNK], xB[CHUNK];
#pragma unroll
    for (int s = 0; s < CHUNK; s++) {
        const int tp = min(s, T - 1);
        xA[s] = xb[(size_t)tp * N_NEU];
    }

    int pb = 0, qb = 1;

    // T must be a multiple of 2*CHUNK (1000 = 50 * 20)
    for (int tc = 0; tc < T; tc += 2 * CHUNK) {
        do_chunk(tc,         T, xA, xB, state, brec, db, W, xb, op, tid,
                 s_idx, s_val, s_cnt, s_flag, pb, qb);
        do_chunk(tc + CHUNK, T, xB, xA, state, brec, db, W, xb, op, tid,
                 s_idx, s_val, s_cnt, s_flag, pb, qb);
    }
}

extern "C" void kernel_launch(void* const* d_in, const int* in_sizes, int n_in,
                              void* d_out, int out_size)
{
    const float* x    = (const float*)d_in[0];   // input_current [B, T, N]
    const float* W    = (const float*)d_in[1];   // w_rec [N, N]
    const float* bias = (const float*)d_in[2];   // b_rec [N]
    float* out = (float*)d_out;

    const int N = in_sizes[2];                   // 1024
    const int T = 1000;
    const int B = in_sizes[0] / (T * N);         // 32

    lif_recurrent_kernel<<<B, THREADS>>>(x, W, bias, out, T);
}